// round 5
// baseline (speedup 1.0000x reference)
#include <cuda_runtime.h>
#include <math.h>

#define FULL 0xffffffffu

constexpr int B = 128, J = 32, I = 1152, N = 16;
constexpr int TI = 16;              // i per tile
constexpr int ROW = TI * N + 4;     // 260: lane*260 mod 32 = lane*4 -> conflict-free LDS.128
constexpr int NCHB = 2;             // blocks per batch
constexpr int IPB = I / NCHB;       // 576
constexpr int TPT = IPB / TI;       // 36 tiles
constexpr int TPB = 256, WARPS = 8;
constexpr int KTH = 8;              // int(0.3*32)-1
constexpr int BUF = J * ROW;        // 8320 floats
constexpr int BB = TI * J + 8;      // 520 floats (b1 tile)
constexpr int REDSTRIDE = 544;
constexpr int SMEM_FLOATS = 2 * BUF + 2 * BB + 512 + 8 + WARPS * REDSTRIDE;

__device__ float g_spart[3][NCHB][B][J * N];
__device__ float g_entp[2][B * NCHB];      // pass1, pass2 entropy partials
__device__ float g_b1[(size_t)B * I * J];  // 18.9 MB masked logits from pass 1

__device__ __forceinline__ float warp_sum(float x) {
#pragma unroll
  for (int m = 16; m; m >>= 1) x += __shfl_xor_sync(FULL, x, m);
  return x;
}
__device__ __forceinline__ float warp_max(float x) {
#pragma unroll
  for (int m = 16; m; m >>= 1) x = fmaxf(x, __shfl_xor_sync(FULL, x, m));
  return x;
}
__device__ __forceinline__ float grp16_sum(float x) {
#pragma unroll
  for (int m = 8; m; m >>= 1) x += __shfl_xor_sync(FULL, x, m);
  return x;
}

// combine two chunk partials -> s; bias + reset + squash -> v (smem)
__device__ __forceinline__ void combine_v(const float* __restrict__ p0,
                                          const float* __restrict__ p1,
                                          const float* __restrict__ bias,
                                          float* vout, int tid) {
#pragma unroll
  for (int r = 0; r < 2; ++r) {
    int e = tid + r * TPB;  // e = j*16+n, 16-groups warp-aligned
    float s = p0[e] + p1[e];
    float ssum = grp16_sum(s);
    float sb = (ssum == 0.f) ? 0.f : s + bias[e];
    float sq = grp16_sum(sb * sb);
    vout[e] = (sq > 0.f) ? sb * (sq / (1.f + sq)) * rsqrtf(sq) : 0.f;
  }
}

template <int ITER>
__global__ void __launch_bounds__(TPB) pass_kernel(const float* __restrict__ u,
                                                   const float* __restrict__ bias) {
  extern __shared__ float smem[];
  float* buf0 = smem;
  float* buf1 = smem + BUF;
  float* bb0 = smem + 2 * BUF;
  float* bb1 = bb0 + BB;
  float* vs = bb1 + BB;     // 512
  float* entw = vs + 512;   // 8
  float* red = entw + 8;

  const int b = blockIdx.y, g = blockIdx.x;
  const int tid = threadIdx.x, w = tid >> 5, lane = tid & 31;
  const int ibase = g * IPB;
  const float NEG_INF = __int_as_float(0xff800000);

  // serpentine: pass1 walks tiles in reverse so it hits what pass0 left in L2
  auto phys = [&](int t) { return (ITER == 1) ? (TPT - 1 - t) : t; };

  auto issue = [&](int pt, int sel) {
    float* buf = sel ? buf1 : buf0;
#pragma unroll
    for (int k = 0; k < 8; ++k) {
      int f = tid + k * TPB;       // 2048 x 16B
      int j = f >> 6, o = f & 63;  // 64 float4 per j-row
      const float* gp = u + (((size_t)b * J + j) * I + (ibase + pt * TI)) * N + o * 4;
      unsigned sa = (unsigned)__cvta_generic_to_shared(buf + j * ROW + o * 4);
      asm volatile("cp.async.cg.shared.global [%0], [%1], 16;\n" ::"r"(sa), "l"(gp));
    }
    if (ITER == 2 && tid < 128) {  // 2KB b1 tile, contiguous
      float* bb = sel ? bb1 : bb0;
      const float* gp = g_b1 + ((size_t)b * I + ibase + pt * TI) * J + tid * 4;
      unsigned sa = (unsigned)__cvta_generic_to_shared(bb + tid * 4);
      asm volatile("cp.async.cg.shared.global [%0], [%1], 16;\n" ::"r"(sa), "l"(gp));
    }
    asm volatile("cp.async.commit_group;\n");
  };

  issue(phys(0), 0);  // overlaps with prologue combine

  if (ITER == 1) combine_v(g_spart[0][0][b], g_spart[0][1][b], bias, vs, tid);
  if (ITER == 2) combine_v(g_spart[1][0][b], g_spart[1][1][b], bias, vs, tid);
  __syncthreads();

  float vr[N];
  if (ITER >= 1) {
#pragma unroll
    for (int n = 0; n < N; ++n) vr[n] = vs[lane * N + n];
  }

  float sacc[N];
#pragma unroll
  for (int n = 0; n < N; ++n) sacc[n] = 0.f;
  float entacc = 0.f;

  for (int t = 0; t < TPT; ++t) {
    const int pt = phys(t);
    if (t + 1 < TPT) {
      issue(phys(t + 1), (t + 1) & 1);
      asm volatile("cp.async.wait_group 1;\n" ::: "memory");
    } else {
      asm volatile("cp.async.wait_group 0;\n" ::: "memory");
    }
    __syncthreads();
    const float* us = (t & 1) ? buf1 : buf0;
    const float* bb = (t & 1) ? bb1 : bb0;

#pragma unroll
    for (int q = 0; q < TI / WARPS; ++q) {  // 2 i per warp
      const int ii = w + q * WARPS;
      float ur[N];
      const float4* up = reinterpret_cast<const float4*>(&us[lane * ROW + ii * N]);
#pragma unroll
      for (int p = 0; p < 4; ++p) {
        float4 x = up[p];
        ur[p * 4 + 0] = x.x; ur[p * 4 + 1] = x.y;
        ur[p * 4 + 2] = x.z; ur[p * 4 + 3] = x.w;
      }

      if (ITER == 0) {  // c = 1/32 (softmax of zeros); scale applied at writeback
#pragma unroll
        for (int n = 0; n < N; ++n) sacc[n] += ur[n];
        continue;
      }

      float cc;
      if (ITER == 1) {
        float d0 = 0.f;
#pragma unroll
        for (int n = 0; n < N; ++n) d0 = fmaf(ur[n], vr[n], d0);
        // bitonic sort over lanes -> kth smallest + max
        float xs = d0;
#pragma unroll
        for (int k = 2; k <= 32; k <<= 1) {
#pragma unroll
          for (int j = k >> 1; j > 0; j >>= 1) {
            float y = __shfl_xor_sync(FULL, xs, j);
            bool take_min = (((lane & j) == 0) == ((lane & k) == 0));
            xs = take_min ? fminf(xs, y) : fmaxf(xs, y);
          }
        }
        float kth = __shfl_sync(FULL, xs, KTH);
        float m = __shfl_sync(FULL, xs, 31);  // max survives masking
        bool msk = (d0 <= kth);
        float bv = msk ? NEG_INF : d0;
        g_b1[((size_t)b * I + ibase + pt * TI + ii) * J + lane] = bv;
        float e = __expf(bv - m);  // exp(-inf) = 0
        float S = warp_sum(e);
        float T = warp_sum(msk ? 0.f : e * (bv - m));
        entacc += __logf(S) - T / S;
        cc = e / S;
      } else {  // ITER == 2: second sparsify is a no-op (kth of column with 9 -infs = -inf)
        float bv = bb[ii * J + lane];
        float d1 = 0.f;
#pragma unroll
        for (int n = 0; n < N; ++n) d1 = fmaf(ur[n], vr[n], d1);
        float b2 = bv + d1;  // -inf propagates
        bool msk = isinf(b2);
        float m = warp_max(b2);
        float e = __expf(b2 - m);
        float S = warp_sum(e);
        float T = warp_sum(msk ? 0.f : e * (b2 - m));
        entacc += __logf(S) - T / S;
        cc = e / S;
      }
#pragma unroll
      for (int n = 0; n < N; ++n) sacc[n] = fmaf(cc, ur[n], sacc[n]);
    }
    __syncthreads();  // readers done before buffer reuse
  }

  if (ITER >= 1 && lane == 0) entw[w] = entacc;
  __syncthreads();
#pragma unroll
  for (int n = 0; n < N; ++n) red[w * REDSTRIDE + lane * 17 + n] = sacc[n];
  __syncthreads();

  float* outp = g_spart[ITER][g][b];
  const float scale = (ITER == 0) ? (1.0f / 32.0f) : 1.0f;
#pragma unroll
  for (int r = 0; r < 2; ++r) {
    int e = tid + r * TPB;
    int jj = e >> 4, nn = e & 15;
    float s = 0.f;
#pragma unroll
    for (int ww = 0; ww < WARPS; ++ww) s += red[ww * REDSTRIDE + jj * 17 + nn];
    outp[e] = s * scale;
  }
  if (ITER >= 1 && tid == 0) {
    float es = 0.f;
#pragma unroll
    for (int ww = 0; ww < WARPS; ++ww) es += entw[ww];
    g_entp[ITER - 1][b * NCHB + g] = es;
  }
}

__global__ void __launch_bounds__(TPB) final_kernel(const float* __restrict__ bias,
                                                    float* __restrict__ out,
                                                    int has_stats) {
  const int tid = threadIdx.x;
  const int idx = blockIdx.x * TPB + tid;
  const int b = idx >> 9, e = idx & 511;

  float s = g_spart[2][0][b][e] + g_spart[2][1][b][e];
  float ssum = grp16_sum(s);
  float sb = (ssum == 0.f) ? 0.f : s + bias[e];
  float sq = grp16_sum(sb * sb);
  out[idx] = (sq > 0.f) ? sb * (sq / (1.f + sq)) * rsqrtf(sq) : 0.f;

  if (has_stats && blockIdx.x == 0) {
    __shared__ float e1[TPB], e2[TPB];
    e1[tid] = g_entp[0][tid];
    e2[tid] = g_entp[1][tid];
    __syncthreads();
    for (int step = TPB / 2; step; step >>= 1) {
      if (tid < step) { e1[tid] += e1[tid + step]; e2[tid] += e2[tid + step]; }
      __syncthreads();
    }
    if (tid == 0) {
      out[B * J * N + 0] = logf(32.0f);  // entropy of uniform softmax
      out[B * J * N + 1] = e1[0] / (float)(B * I);
      out[B * J * N + 2] = e2[0] / (float)(B * I);
    }
  }
}

extern "C" void kernel_launch(void* const* d_in, const int* in_sizes, int n_in,
                              void* d_out, int out_size) {
  const float* u = (const float*)d_in[0];
  const float* bias = (const float*)d_in[1];
  float* out = (float*)d_out;
  const int has_stats = (out_size >= B * J * N + 3) ? 1 : 0;

  const size_t sh = SMEM_FLOATS * sizeof(float);  // ~90 KB -> 2 blocks/SM
  cudaFuncSetAttribute(pass_kernel<0>, cudaFuncAttributeMaxDynamicSharedMemorySize, (int)sh);
  cudaFuncSetAttribute(pass_kernel<1>, cudaFuncAttributeMaxDynamicSharedMemorySize, (int)sh);
  cudaFuncSetAttribute(pass_kernel<2>, cudaFuncAttributeMaxDynamicSharedMemorySize, (int)sh);

  dim3 grid(NCHB, B);
  pass_kernel<0><<<grid, TPB, sh>>>(u, bias);
  pass_kernel<1><<<grid, TPB, sh>>>(u, bias);
  pass_kernel<2><<<grid, TPB, sh>>>(u, bias);
  final_kernel<<<(B * J * N) / TPB, TPB>>>(bias, out, has_stats);
}

// round 6
// speedup vs baseline: 1.0752x; 1.0752x over previous
#include <cuda_runtime.h>
#include <math.h>

#define FULL 0xffffffffu

constexpr int B = 128, J = 32, I = 1152, N = 16;
constexpr int TI = 16;             // i per tile (passes 1-2)
constexpr int ROW = TI * N + 4;    // 260: conflict-free LDS.128
constexpr int NCHB = 2;            // blocks per batch
constexpr int IPB = I / NCHB;      // 576
constexpr int TPT = IPB / TI;      // 36 tiles
constexpr int TPB = 256, WARPS = 8;
constexpr int KTH = 8;             // int(0.3*32)-1
constexpr int BUF = J * ROW;       // 8320 floats
constexpr int REDSTRIDE = 544;
constexpr int SMEM_FLOATS = 2 * BUF + 512 + 8 + WARPS * REDSTRIDE + IPB;

__device__ float g_spart[3][NCHB][B][J * N];
__device__ float g_entp[2][B * NCHB];
__device__ int g_sync[B][3];

__device__ __forceinline__ float warp_sum(float x) {
#pragma unroll
  for (int m = 16; m; m >>= 1) x += __shfl_xor_sync(FULL, x, m);
  return x;
}
__device__ __forceinline__ float grp16_sum(float x) {
#pragma unroll
  for (int m = 8; m; m >>= 1) x += __shfl_xor_sync(FULL, x, m);
  return x;
}

// combine two chunk partials (via L2) -> s; bias + reset + squash -> v (smem)
__device__ __forceinline__ void combine_v(const float* __restrict__ p0,
                                          const float* __restrict__ p1,
                                          const float* __restrict__ bias,
                                          float* vout, int tid) {
#pragma unroll
  for (int r = 0; r < 2; ++r) {
    int e = tid + r * TPB;  // e = j*16+n, 16-groups warp-aligned
    float s = __ldcg(p0 + e) + __ldcg(p1 + e);
    float ssum = grp16_sum(s);
    float sb = (ssum == 0.f) ? 0.f : s + bias[e];
    float sq = grp16_sum(sb * sb);
    vout[e] = (sq > 0.f) ? sb * (sq / (1.f + sq)) * rsqrtf(sq) : 0.f;
  }
}

__global__ void __launch_bounds__(TPB, 2) routing_kernel(const float* __restrict__ u,
                                                         const float* __restrict__ bias,
                                                         float* __restrict__ out) {
  extern __shared__ float smem[];
  float* buf0 = smem;
  float* buf1 = smem + BUF;
  float* vs = smem + 2 * BUF;  // 512
  float* entw = vs + 512;      // 8
  float* red = entw + 8;       // 4352
  unsigned* maskb = (unsigned*)(red + WARPS * REDSTRIDE);  // 576

  const int b = blockIdx.y, g = blockIdx.x;
  const int tid = threadIdx.x, w = tid >> 5, lane = tid & 31;
  const int ibase = g * IPB;

  auto issue = [&](int pt, int sel) {
    float* buf = sel ? buf1 : buf0;
#pragma unroll
    for (int k = 0; k < 8; ++k) {
      int f = tid + k * TPB;       // 2048 x 16B
      int j = f >> 6, o = f & 63;  // 64 float4 per j-row
      const float* gp = u + (((size_t)b * J + j) * I + (ibase + pt * TI)) * N + o * 4;
      unsigned sa = (unsigned)__cvta_generic_to_shared(buf + j * ROW + o * 4);
      asm volatile("cp.async.cg.shared.global [%0], [%1], 16;\n" ::"r"(sa), "l"(gp));
    }
    asm volatile("cp.async.commit_group;\n");
  };

  auto signal_wait = [&](int ph) {
    __threadfence();
    __syncthreads();
    if (tid == 0) {
      atomicAdd(&g_sync[b][ph], 1);
      while (atomicAdd(&g_sync[b][ph], 0) < 2) {}
      __threadfence();
    }
    __syncthreads();
  };

  // ================= PASS 0: direct streaming sum, c = 1/32 =================
  {
    const int half = tid >> 7, t2 = tid & 127, j0 = t2 >> 2, n4 = t2 & 3;
    const float4* p =
        (const float4*)(u + (((size_t)b * J + j0) * I + ibase + half * (IPB / 2)) * N) + n4;
    float4 a = make_float4(0.f, 0.f, 0.f, 0.f);
#pragma unroll 8
    for (int i = 0; i < IPB / 2; ++i) {
      float4 x = p[i * 4];
      a.x += x.x; a.y += x.y; a.z += x.z; a.w += x.w;
    }
    float4* rf = (float4*)red;
    rf[tid] = a;
    __syncthreads();
    if (tid < 128) {
      float4 a0 = rf[tid], a1 = rf[tid + 128];
      float4 s = make_float4((a0.x + a1.x) * (1.f / 32.f), (a0.y + a1.y) * (1.f / 32.f),
                             (a0.z + a1.z) * (1.f / 32.f), (a0.w + a1.w) * (1.f / 32.f));
      __stcg((float4*)(g_spart[0][g][b] + j0 * 16 + n4 * 4), s);
    }
  }

  issue(TPT - 1, 0);  // prefetch pass-1 first tile (reverse order) during handshake
  signal_wait(0);
  combine_v(g_spart[0][0][b], g_spart[0][1][b], bias, vs, tid);
  __syncthreads();

  float vr0[N];
#pragma unroll
  for (int n = 0; n < N; ++n) vr0[n] = vs[lane * N + n];

  // ================= PASS 1: sort + mask + softmax (reverse tiles) ==========
  float sacc[N];
#pragma unroll
  for (int n = 0; n < N; ++n) sacc[n] = 0.f;
  float eu = 0.f, el = 0.f;

  for (int t = 0; t < TPT; ++t) {
    const int pt = TPT - 1 - t;
    if (t + 1 < TPT) {
      issue(TPT - 2 - t, (t + 1) & 1);
      asm volatile("cp.async.wait_group 1;\n" ::: "memory");
    } else {
      asm volatile("cp.async.wait_group 0;\n" ::: "memory");
    }
    __syncthreads();
    const float* us = (t & 1) ? buf1 : buf0;

#pragma unroll
    for (int q = 0; q < 2; ++q) {
      const int ii = w + q * WARPS;
      float ur[N];
      const float4* up = reinterpret_cast<const float4*>(&us[lane * ROW + ii * N]);
#pragma unroll
      for (int p = 0; p < 4; ++p) {
        float4 x = up[p];
        ur[p * 4 + 0] = x.x; ur[p * 4 + 1] = x.y;
        ur[p * 4 + 2] = x.z; ur[p * 4 + 3] = x.w;
      }
      float d0 = 0.f;
#pragma unroll
      for (int n = 0; n < N; ++n) d0 = fmaf(ur[n], vr0[n], d0);
      // bitonic sort over lanes -> kth smallest
      float xs = d0;
#pragma unroll
      for (int k = 2; k <= 32; k <<= 1) {
#pragma unroll
        for (int j = k >> 1; j > 0; j >>= 1) {
          float y = __shfl_xor_sync(FULL, xs, j);
          bool take_min = (((lane & j) == 0) == ((lane & k) == 0));
          xs = take_min ? fminf(xs, y) : fmaxf(xs, y);
        }
      }
      float kth = __shfl_sync(FULL, xs, KTH);
      bool msk = (d0 <= kth);
      unsigned bal = __ballot_sync(FULL, msk);
      if (lane == 0) maskb[pt * TI + ii] = bal;
      float e = msk ? 0.f : __expf(d0);  // no max-sub: |d0| <= ~6 (||v0||<1)
      float S = warp_sum(e);
      float cc = e / S;
      eu += __logf(S);
      el = fmaf(cc, d0, el);  // cc=0 when masked
#pragma unroll
      for (int n = 0; n < N; ++n) sacc[n] = fmaf(cc, ur[n], sacc[n]);
    }
    __syncthreads();
  }

  // pass-1 writeback
  {
    float ent = eu - warp_sum(el);
    if (lane == 0) entw[w] = ent;
#pragma unroll
    for (int n = 0; n < N; ++n) red[w * REDSTRIDE + lane * 17 + n] = sacc[n];
    __syncthreads();
#pragma unroll
    for (int r = 0; r < 2; ++r) {
      int e = tid + r * TPB;
      int jj = e >> 4, nn = e & 15;
      float s = 0.f;
#pragma unroll
      for (int ww = 0; ww < WARPS; ++ww) s += red[ww * REDSTRIDE + jj * 17 + nn];
      __stcg(&g_spart[1][g][b][e], s);
    }
    if (tid == 0) {
      float es = 0.f;
#pragma unroll
      for (int ww = 0; ww < WARPS; ++ww) es += entw[ww];
      g_entp[0][b * NCHB + g] = es;
    }
  }

  issue(0, 0);  // prefetch pass-2 first tile (forward order)
  signal_wait(1);
  combine_v(g_spart[1][0][b], g_spart[1][1][b], bias, vs, tid);
  __syncthreads();

  float wr[N];
#pragma unroll
  for (int n = 0; n < N; ++n) wr[n] = vr0[n] + vs[lane * N + n];  // w = v0 + v1

  // ================= PASS 2: mask-propagated softmax (forward tiles) ========
#pragma unroll
  for (int n = 0; n < N; ++n) sacc[n] = 0.f;
  eu = 0.f; el = 0.f;

  for (int t = 0; t < TPT; ++t) {
    const int pt = t;
    if (t + 1 < TPT) {
      issue(t + 1, (t + 1) & 1);
      asm volatile("cp.async.wait_group 1;\n" ::: "memory");
    } else {
      asm volatile("cp.async.wait_group 0;\n" ::: "memory");
    }
    __syncthreads();
    const float* us = (t & 1) ? buf1 : buf0;

#pragma unroll
    for (int q = 0; q < 2; ++q) {
      const int ii = w + q * WARPS;
      float ur[N];
      const float4* up = reinterpret_cast<const float4*>(&us[lane * ROW + ii * N]);
#pragma unroll
      for (int p = 0; p < 4; ++p) {
        float4 x = up[p];
        ur[p * 4 + 0] = x.x; ur[p * 4 + 1] = x.y;
        ur[p * 4 + 2] = x.z; ur[p * 4 + 3] = x.w;
      }
      float d = 0.f;  // b2 (unmasked) = d0 + d1 = u . (v0+v1)
#pragma unroll
      for (int n = 0; n < N; ++n) d = fmaf(ur[n], wr[n], d);
      bool msk = (maskb[pt * TI + ii] >> lane) & 1;
      float e = msk ? 0.f : __expf(d);
      float S = warp_sum(e);
      float cc = e / S;
      eu += __logf(S);
      el = fmaf(cc, d, el);
#pragma unroll
      for (int n = 0; n < N; ++n) sacc[n] = fmaf(cc, ur[n], sacc[n]);
    }
    __syncthreads();
  }

  // pass-2 writeback
  {
    float ent = eu - warp_sum(el);
    if (lane == 0) entw[w] = ent;
#pragma unroll
    for (int n = 0; n < N; ++n) red[w * REDSTRIDE + lane * 17 + n] = sacc[n];
    __syncthreads();
#pragma unroll
    for (int r = 0; r < 2; ++r) {
      int e = tid + r * TPB;
      int jj = e >> 4, nn = e & 15;
      float s = 0.f;
#pragma unroll
      for (int ww = 0; ww < WARPS; ++ww) s += red[ww * REDSTRIDE + jj * 17 + nn];
      __stcg(&g_spart[2][g][b][e], s);
    }
    if (tid == 0) {
      float es = 0.f;
#pragma unroll
      for (int ww = 0; ww < WARPS; ++ww) es += entw[ww];
      g_entp[1][b * NCHB + g] = es;
    }
  }

  signal_wait(2);

  // final combine + squash -> out (each block writes its half of the 512)
  {
    int e = g * TPB + tid;
    float s = __ldcg(g_spart[2][0][b] + e) + __ldcg(g_spart[2][1][b] + e);
    float ssum = grp16_sum(s);
    float sb = (ssum == 0.f) ? 0.f : s + bias[e];
    float sq = grp16_sum(sb * sb);
    out[b * (J * N) + e] = (sq > 0.f) ? sb * (sq / (1.f + sq)) * rsqrtf(sq) : 0.f;
  }
}

__global__ void reset_kernel() {
  int t = blockIdx.x * blockDim.x + threadIdx.x;
  if (t < B * 3) ((int*)g_sync)[t] = 0;
}

__global__ void __launch_bounds__(TPB) stats_kernel(float* __restrict__ out, int has_stats) {
  if (!has_stats) return;
  __shared__ float e1[TPB], e2[TPB];
  const int tid = threadIdx.x;
  e1[tid] = g_entp[0][tid];
  e2[tid] = g_entp[1][tid];
  __syncthreads();
  for (int step = TPB / 2; step; step >>= 1) {
    if (tid < step) { e1[tid] += e1[tid + step]; e2[tid] += e2[tid + step]; }
    __syncthreads();
  }
  if (tid == 0) {
    out[B * J * N + 0] = logf(32.0f);  // entropy of uniform softmax (iter 0)
    out[B * J * N + 1] = e1[0] / (float)(B * I);
    out[B * J * N + 2] = e2[0] / (float)(B * I);
  }
}

extern "C" void kernel_launch(void* const* d_in, const int* in_sizes, int n_in,
                              void* d_out, int out_size) {
  const float* u = (const float*)d_in[0];
  const float* bias = (const float*)d_in[1];
  float* out = (float*)d_out;
  const int has_stats = (out_size >= B * J * N + 3) ? 1 : 0;

  const size_t sh = SMEM_FLOATS * sizeof(float);  // ~86.3 KB -> 2 blocks/SM
  cudaFuncSetAttribute(routing_kernel, cudaFuncAttributeMaxDynamicSharedMemorySize, (int)sh);

  reset_kernel<<<2, 256>>>();
  routing_kernel<<<dim3(NCHB, B), TPB, sh>>>(u, bias, out);
  stats_kernel<<<1, TPB>>>(out, has_stats);
}